// round 4
// baseline (speedup 1.0000x reference)
#include <cuda_runtime.h>
#include <cuda_bf16.h>
#include <mma.h>
#include <cstdint>

using namespace nvcuda;

#define Bb 32
#define Cc 32
#define Tt 2048
#define Dd 512
#define ALPHA 0.1f
#define BETA  0.9f

#define SEG   256      // scan segment length
#define NSEG  (Tt / SEG)

// Scratch (no cudaMalloc allowed)
__device__ float g_sA[Bb*Cc*Tt];            // 0.5 * forward EWMA of diff   [b][c][t]
__device__ float g_sB[Bb*Cc*Tt];            // 0.5 * backward EWMA of diff  [b][c][t]
__device__ __nv_bfloat16 g_whi[Dd*Cc];      // hi(W_lin @ W_ve)[e][c]
__device__ __nv_bfloat16 g_wlo[Dd*Cc];      // lo residual
__device__ float g_bcomb[Dd];               // W_lin @ b_ve + b_lin

// ---------------------------------------------------------------------------
// P: compose linears; emit bf16 hi/lo split of Wcomb.
// ---------------------------------------------------------------------------
__global__ void __launch_bounds__(256) prep_kernel(
    const float* __restrict__ W_ve, const float* __restrict__ b_ve,
    const float* __restrict__ W_lin, const float* __restrict__ b_lin)
{
    __shared__ float wl[Dd];
    int e = blockIdx.x;
    int tid = threadIdx.x;
    wl[tid]       = W_lin[(size_t)e * Dd + tid];
    wl[tid + 256] = W_lin[(size_t)e * Dd + tid + 256];
    __syncthreads();

    int wj   = tid >> 5;
    int lane = tid & 31;
    const unsigned FULL = 0xffffffffu;

    for (int c = wj; c <= Cc; c += 8) {
        float acc = 0.f;
        if (c < Cc) {
            #pragma unroll
            for (int i = 0; i < 16; i++) {
                int d = lane + 32 * i;
                acc = fmaf(wl[d], W_ve[d * Cc + c], acc);
            }
        } else {
            #pragma unroll
            for (int i = 0; i < 16; i++) {
                int d = lane + 32 * i;
                acc = fmaf(wl[d], b_ve[d], acc);
            }
        }
        acc += __shfl_down_sync(FULL, acc, 16);
        acc += __shfl_down_sync(FULL, acc, 8);
        acc += __shfl_down_sync(FULL, acc, 4);
        acc += __shfl_down_sync(FULL, acc, 2);
        acc += __shfl_down_sync(FULL, acc, 1);
        if (lane == 0) {
            if (c < Cc) {
                __nv_bfloat16 h = __float2bfloat16(acc);
                g_whi[e * Cc + c] = h;
                g_wlo[e * Cc + c] = __float2bfloat16(acc - __bfloat162float(h));
            } else {
                g_bcomb[e] = acc + b_lin[e];
            }
        }
    }
}

// ---------------------------------------------------------------------------
// S: bidirectional EWMA of first-difference (unchanged from round 3).
// ---------------------------------------------------------------------------
__global__ void __launch_bounds__(256) scan_kernel(const float* __restrict__ x)
{
    const unsigned FULL = 0xffffffffu;
    int g    = blockIdx.x * 8 + (threadIdx.x >> 5);
    int lane = threadIdx.x & 31;
    int bc   = g >> 4;           // row (b*Cc + c)
    int rem  = g & 15;
    int seg  = rem >> 1;
    int dir  = rem & 1;

    const float* row = x + (size_t)bc * Tt;
    int lo = seg * SEG;
    int hi = lo + SEG;

    const float q   = 0.43046721f;              // 0.9^8
    const float q2  = q * q;
    const float q4  = q2 * q2;
    const float q8  = q4 * q4;
    const float q16 = q8 * q8;
    float blE;
    {
        float p = 1.f, base = q;
        int n = lane;
        while (n) { if (n & 1) p *= base; base *= base; n >>= 1; }
        blE = p;
    }
    const float B256 = 1.9e-12f;

    if (dir == 0) {
        float* srow = g_sA + (size_t)bc * Tt;
        int t0 = (seg == 0) ? lo : (lo - SEG);
        float warpCarry = 0.f;
        for (; t0 < hi; t0 += SEG) {
            int tb = t0 + lane * 8;
            float4 a  = *(const float4*)(row + tb);
            float4 bq = *(const float4*)(row + tb + 4);
            float e[8] = {a.x, a.y, a.z, a.w, bq.x, bq.y, bq.z, bq.w};
            float prev = __shfl_up_sync(FULL, bq.w, 1);
            if (lane == 0) prev = (tb > 0) ? row[tb - 1] : 0.f;

            float L[8];
            L[0] = (tb == 0) ? 0.f : ALPHA * (e[0] - prev);
            #pragma unroll
            for (int j = 1; j < 8; j++)
                L[j] = fmaf(BETA, L[j - 1], ALPHA * (e[j] - e[j - 1]));

            float v = L[7], vo;
            vo = __shfl_up_sync(FULL, v, 1);  if (lane >= 1)  v = fmaf(q,   vo, v);
            vo = __shfl_up_sync(FULL, v, 2);  if (lane >= 2)  v = fmaf(q2,  vo, v);
            vo = __shfl_up_sync(FULL, v, 4);  if (lane >= 4)  v = fmaf(q4,  vo, v);
            vo = __shfl_up_sync(FULL, v, 8);  if (lane >= 8)  v = fmaf(q8,  vo, v);
            vo = __shfl_up_sync(FULL, v, 16); if (lane >= 16) v = fmaf(q16, vo, v);
            float vprev = __shfl_up_sync(FULL, v, 1);
            if (lane == 0) vprev = 0.f;
            float C = fmaf(blE, warpCarry, vprev);

            float F[8];
            {
                float coef = BETA;
                #pragma unroll
                for (int j = 0; j < 8; j++) { F[j] = fmaf(coef, C, L[j]); coef *= BETA; }
            }
            float v31 = __shfl_sync(FULL, v, 31);
            warpCarry = fmaf(B256, warpCarry, v31);

            if (t0 >= lo) {
                *(float4*)(srow + tb)     = make_float4(0.5f*F[0], 0.5f*F[1], 0.5f*F[2], 0.5f*F[3]);
                *(float4*)(srow + tb + 4) = make_float4(0.5f*F[4], 0.5f*F[5], 0.5f*F[6], 0.5f*F[7]);
            }
        }
    } else {
        float* srow = g_sB + (size_t)bc * Tt;
        bool last = (hi == Tt);
        int tt = last ? (Tt - 1) : (hi + SEG - 1);
        float warpCarry = last ? (row[Tt - 1] - row[Tt - 2]) : 0.f;
        for (; tt >= lo; tt -= SEG) {
            int tb = tt - lane * 8;
            float4 a  = *(const float4*)(row + tb - 7);
            float4 bq = *(const float4*)(row + tb - 3);
            float e[8] = {bq.w, bq.z, bq.y, bq.x, a.w, a.z, a.y, a.x};
            float prev = __shfl_down_sync(FULL, bq.w, 1);
            if (lane == 31) prev = (tb - 8 >= 0) ? row[tb - 8] : 0.f;

            float L[8];
            L[0] = ALPHA * (e[0] - e[1]);
            #pragma unroll
            for (int j = 1; j < 7; j++)
                L[j] = fmaf(BETA, L[j - 1], ALPHA * (e[j] - e[j + 1]));
            {
                float d7 = (tb - 7 == 0) ? 0.f : (e[7] - prev);
                L[7] = fmaf(BETA, L[6], ALPHA * d7);
            }

            float v = L[7], vo;
            vo = __shfl_up_sync(FULL, v, 1);  if (lane >= 1)  v = fmaf(q,   vo, v);
            vo = __shfl_up_sync(FULL, v, 2);  if (lane >= 2)  v = fmaf(q2,  vo, v);
            vo = __shfl_up_sync(FULL, v, 4);  if (lane >= 4)  v = fmaf(q4,  vo, v);
            vo = __shfl_up_sync(FULL, v, 8);  if (lane >= 8)  v = fmaf(q8,  vo, v);
            vo = __shfl_up_sync(FULL, v, 16); if (lane >= 16) v = fmaf(q16, vo, v);
            float vprev = __shfl_up_sync(FULL, v, 1);
            if (lane == 0) vprev = 0.f;
            float C = fmaf(blE, warpCarry, vprev);

            float F[8];
            {
                float coef = BETA;
                #pragma unroll
                for (int j = 0; j < 8; j++) { F[j] = fmaf(coef, C, L[j]); coef *= BETA; }
            }
            float v31 = __shfl_sync(FULL, v, 31);
            warpCarry = fmaf(B256, warpCarry, v31);

            if (tt < hi) {
                *(float4*)(srow + tb - 7) = make_float4(0.5f*F[7], 0.5f*F[6], 0.5f*F[5], 0.5f*F[4]);
                *(float4*)(srow + tb - 3) = make_float4(0.5f*F[3], 0.5f*F[2], 0.5f*F[1], 0.5f*F[0]);
            }
        }
    }
}

// ---------------------------------------------------------------------------
// G: split-bf16 tensor-core GEMM.
// out[b,t,e] = sum_c s[c,t]*W[e,c] + bias[e],  s = hi+lo, W = hi+lo (bf16).
// D = Sh*Wh + Sh*Wl + Sl*Wh  (Sl*Wl ~ 2^-18, dropped).
// Block: 256 thr (8 warps), tile 128 t x 512 e (e in 4 chunks of 128).
// Warp w owns t-strip [w*16, w*16+16); wmma m16n16k16, K=32 = 2 k-steps.
// ---------------------------------------------------------------------------
__global__ void __launch_bounds__(256) gemm_kernel(float* __restrict__ out)
{
    __shared__ __nv_bfloat16 Sh[128][40];   // [t][c], ld 40 (mult of 8)
    __shared__ __nv_bfloat16 Sl[128][40];
    __shared__ __nv_bfloat16 Wh[128][32];   // [e_local][c]
    __shared__ __nv_bfloat16 Wl[128][32];
    __shared__ float scratch[8][256];       // per-warp 16x16 epilogue tile

    int tid  = threadIdx.x;
    int warp = tid >> 5;
    int lane = tid & 31;
    int b = blockIdx.y;
    int tBase = blockIdx.x * 128;

    // Load s tile: 4096 elems; idx -> (t = idx&127, c = idx>>7). Coalesced in t.
    #pragma unroll
    for (int k = 0; k < 16; k++) {
        int idx = tid + k * 256;
        int t = idx & 127;
        int c = idx >> 7;
        size_t off = ((size_t)(b * Cc + c)) * Tt + tBase + t;
        float s = g_sA[off] + g_sB[off];
        __nv_bfloat16 h = __float2bfloat16(s);
        Sh[t][c] = h;
        Sl[t][c] = __float2bfloat16(s - __bfloat162float(h));
    }
    __syncthreads();

    // Per-warp A fragments (reused across all e)
    wmma::fragment<wmma::matrix_a, 16, 16, 16, __nv_bfloat16, wmma::row_major> ah0, ah1, al0, al1;
    wmma::load_matrix_sync(ah0, &Sh[warp * 16][0],  40);
    wmma::load_matrix_sync(ah1, &Sh[warp * 16][16], 40);
    wmma::load_matrix_sync(al0, &Sl[warp * 16][0],  40);
    wmma::load_matrix_sync(al1, &Sl[warp * 16][16], 40);

    for (int ch = 0; ch < 4; ch++) {
        int eBase = ch * 128;
        __syncthreads();   // previous chunk readers done with Wh/Wl
        // Copy W chunk (bf16, contiguous): 4096 bf16 per array = 2048 words
        {
            const int* srcH = (const int*)(g_whi + (size_t)eBase * Cc);
            const int* srcL = (const int*)(g_wlo + (size_t)eBase * Cc);
            int* dstH = (int*)&Wh[0][0];
            int* dstL = (int*)&Wl[0][0];
            #pragma unroll
            for (int k = 0; k < 8; k++) {
                dstH[tid + k * 256] = srcH[tid + k * 256];
                dstL[tid + k * 256] = srcL[tid + k * 256];
            }
        }
        __syncthreads();

        #pragma unroll
        for (int et = 0; et < 8; et++) {
            wmma::fragment<wmma::matrix_b, 16, 16, 16, __nv_bfloat16, wmma::col_major> bh0, bh1, bl0, bl1;
            wmma::load_matrix_sync(bh0, &Wh[et * 16][0],  32);
            wmma::load_matrix_sync(bh1, &Wh[et * 16][16], 32);
            wmma::load_matrix_sync(bl0, &Wl[et * 16][0],  32);
            wmma::load_matrix_sync(bl1, &Wl[et * 16][16], 32);

            wmma::fragment<wmma::accumulator, 16, 16, 16, float> acc;
            wmma::fill_fragment(acc, 0.f);
            wmma::mma_sync(acc, ah0, bh0, acc);
            wmma::mma_sync(acc, ah1, bh1, acc);
            wmma::mma_sync(acc, ah0, bl0, acc);
            wmma::mma_sync(acc, ah1, bl1, acc);
            wmma::mma_sync(acc, al0, bh0, acc);
            wmma::mma_sync(acc, al1, bh1, acc);

            wmma::store_matrix_sync(&scratch[warp][0], acc, 16, wmma::mem_row_major);
            __syncwarp();

            int e0 = eBase + et * 16;
            #pragma unroll
            for (int k = 0; k < 8; k++) {
                int idx = lane + k * 32;       // 0..255
                int r = idx >> 4;
                int cc = idx & 15;
                float v = scratch[warp][idx] + g_bcomb[e0 + cc];
                int t = tBase + warp * 16 + r;
                out[((size_t)(b * Tt + t)) * Dd + e0 + cc] = v;
            }
            __syncwarp();   // before next store_matrix_sync overwrites scratch
        }
    }
}

// ---------------------------------------------------------------------------
extern "C" void kernel_launch(void* const* d_in, const int* in_sizes, int n_in,
                              void* d_out, int out_size)
{
    const float* x     = (const float*)d_in[0];   // [B, C, T]
    const float* W_ve  = (const float*)d_in[1];   // [D, C]
    const float* b_ve  = (const float*)d_in[2];   // [D]
    const float* W_lin = (const float*)d_in[3];   // [D, D]
    const float* b_lin = (const float*)d_in[4];   // [D]
    float* out = (float*)d_out;                   // [B, T, D]

    // S: 16384 segment-warps (rows x 8 segs x 2 dirs), 8 warps/block
    scan_kernel<<<(Bb * Cc * NSEG * 2) / 8, 256>>>(x);

    // P: compose linears, bf16 split
    prep_kernel<<<Dd, 256>>>(W_ve, b_ve, W_lin, b_lin);

    // G: tensor-core GEMM + bias
    dim3 grid(Tt / 128, Bb);
    gemm_kernel<<<grid, 256>>>(out);
}

// round 5
// speedup vs baseline: 1.0420x; 1.0420x over previous
#include <cuda_runtime.h>
#include <cuda_bf16.h>
#include <mma.h>
#include <cstdint>

using namespace nvcuda;

#define Bb 32
#define Cc 32
#define Tt 2048
#define Dd 512
#define ALPHA 0.1f
#define BETA  0.9f

#define SEG   256      // scan segment length
#define NSEG  (Tt / SEG)
#define KP    48       // padded K (32 channels + bias channel + zeros)

// Scratch (no cudaMalloc allowed)
__device__ float g_sA[Bb*Cc*Tt];            // 0.5 * forward EWMA of diff   [b][c][t]
__device__ float g_sB[Bb*Cc*Tt];            // 0.5 * backward EWMA of diff  [b][c][t]
__device__ __nv_bfloat16 g_whi[Dd*KP];      // hi(Wcomb), bias-hi at c=32, 0 pad
__device__ __nv_bfloat16 g_wlo[Dd*KP];      // lo residual, bias-lo at c=32

// ---------------------------------------------------------------------------
// P: compose linears; emit bf16 hi/lo split of Wcomb padded to KP columns,
// with the combined bias (hi/lo) in column 32.
// ---------------------------------------------------------------------------
__global__ void __launch_bounds__(256) prep_kernel(
    const float* __restrict__ W_ve, const float* __restrict__ b_ve,
    const float* __restrict__ W_lin, const float* __restrict__ b_lin)
{
    __shared__ float wl[Dd];
    int e = blockIdx.x;
    int tid = threadIdx.x;
    wl[tid]       = W_lin[(size_t)e * Dd + tid];
    wl[tid + 256] = W_lin[(size_t)e * Dd + tid + 256];
    if (tid < KP) {             // zero pad columns (c=33..47 stay zero)
        g_whi[e * KP + tid] = __float2bfloat16(0.f);
        g_wlo[e * KP + tid] = __float2bfloat16(0.f);
    }
    __syncthreads();

    int wj   = tid >> 5;
    int lane = tid & 31;
    const unsigned FULL = 0xffffffffu;

    for (int c = wj; c <= Cc; c += 8) {
        float acc = 0.f;
        if (c < Cc) {
            #pragma unroll
            for (int i = 0; i < 16; i++) {
                int d = lane + 32 * i;
                acc = fmaf(wl[d], W_ve[d * Cc + c], acc);
            }
        } else {
            #pragma unroll
            for (int i = 0; i < 16; i++) {
                int d = lane + 32 * i;
                acc = fmaf(wl[d], b_ve[d], acc);
            }
        }
        acc += __shfl_down_sync(FULL, acc, 16);
        acc += __shfl_down_sync(FULL, acc, 8);
        acc += __shfl_down_sync(FULL, acc, 4);
        acc += __shfl_down_sync(FULL, acc, 2);
        acc += __shfl_down_sync(FULL, acc, 1);
        if (lane == 0) {
            if (c == Cc) acc += b_lin[e];          // bias channel
            __nv_bfloat16 h = __float2bfloat16(acc);
            g_whi[e * KP + c] = h;
            g_wlo[e * KP + c] = __float2bfloat16(acc - __bfloat162float(h));
        }
    }
}

// ---------------------------------------------------------------------------
// S: bidirectional EWMA of first-difference (unchanged).
// ---------------------------------------------------------------------------
__global__ void __launch_bounds__(256) scan_kernel(const float* __restrict__ x)
{
    const unsigned FULL = 0xffffffffu;
    int g    = blockIdx.x * 8 + (threadIdx.x >> 5);
    int lane = threadIdx.x & 31;
    int bc   = g >> 4;
    int rem  = g & 15;
    int seg  = rem >> 1;
    int dir  = rem & 1;

    const float* row = x + (size_t)bc * Tt;
    int lo = seg * SEG;
    int hi = lo + SEG;

    const float q   = 0.43046721f;              // 0.9^8
    const float q2  = q * q;
    const float q4  = q2 * q2;
    const float q8  = q4 * q4;
    const float q16 = q8 * q8;
    float blE;
    {
        float p = 1.f, base = q;
        int n = lane;
        while (n) { if (n & 1) p *= base; base *= base; n >>= 1; }
        blE = p;
    }
    const float B256 = 1.9e-12f;

    if (dir == 0) {
        float* srow = g_sA + (size_t)bc * Tt;
        int t0 = (seg == 0) ? lo : (lo - SEG);
        float warpCarry = 0.f;
        for (; t0 < hi; t0 += SEG) {
            int tb = t0 + lane * 8;
            float4 a  = *(const float4*)(row + tb);
            float4 bq = *(const float4*)(row + tb + 4);
            float e[8] = {a.x, a.y, a.z, a.w, bq.x, bq.y, bq.z, bq.w};
            float prev = __shfl_up_sync(FULL, bq.w, 1);
            if (lane == 0) prev = (tb > 0) ? row[tb - 1] : 0.f;

            float L[8];
            L[0] = (tb == 0) ? 0.f : ALPHA * (e[0] - prev);
            #pragma unroll
            for (int j = 1; j < 8; j++)
                L[j] = fmaf(BETA, L[j - 1], ALPHA * (e[j] - e[j - 1]));

            float v = L[7], vo;
            vo = __shfl_up_sync(FULL, v, 1);  if (lane >= 1)  v = fmaf(q,   vo, v);
            vo = __shfl_up_sync(FULL, v, 2);  if (lane >= 2)  v = fmaf(q2,  vo, v);
            vo = __shfl_up_sync(FULL, v, 4);  if (lane >= 4)  v = fmaf(q4,  vo, v);
            vo = __shfl_up_sync(FULL, v, 8);  if (lane >= 8)  v = fmaf(q8,  vo, v);
            vo = __shfl_up_sync(FULL, v, 16); if (lane >= 16) v = fmaf(q16, vo, v);
            float vprev = __shfl_up_sync(FULL, v, 1);
            if (lane == 0) vprev = 0.f;
            float C = fmaf(blE, warpCarry, vprev);

            float F[8];
            {
                float coef = BETA;
                #pragma unroll
                for (int j = 0; j < 8; j++) { F[j] = fmaf(coef, C, L[j]); coef *= BETA; }
            }
            float v31 = __shfl_sync(FULL, v, 31);
            warpCarry = fmaf(B256, warpCarry, v31);

            if (t0 >= lo) {
                *(float4*)(srow + tb)     = make_float4(0.5f*F[0], 0.5f*F[1], 0.5f*F[2], 0.5f*F[3]);
                *(float4*)(srow + tb + 4) = make_float4(0.5f*F[4], 0.5f*F[5], 0.5f*F[6], 0.5f*F[7]);
            }
        }
    } else {
        float* srow = g_sB + (size_t)bc * Tt;
        bool last = (hi == Tt);
        int tt = last ? (Tt - 1) : (hi + SEG - 1);
        float warpCarry = last ? (row[Tt - 1] - row[Tt - 2]) : 0.f;
        for (; tt >= lo; tt -= SEG) {
            int tb = tt - lane * 8;
            float4 a  = *(const float4*)(row + tb - 7);
            float4 bq = *(const float4*)(row + tb - 3);
            float e[8] = {bq.w, bq.z, bq.y, bq.x, a.w, a.z, a.y, a.x};
            float prev = __shfl_down_sync(FULL, bq.w, 1);
            if (lane == 31) prev = (tb - 8 >= 0) ? row[tb - 8] : 0.f;

            float L[8];
            L[0] = ALPHA * (e[0] - e[1]);
            #pragma unroll
            for (int j = 1; j < 7; j++)
                L[j] = fmaf(BETA, L[j - 1], ALPHA * (e[j] - e[j + 1]));
            {
                float d7 = (tb - 7 == 0) ? 0.f : (e[7] - prev);
                L[7] = fmaf(BETA, L[6], ALPHA * d7);
            }

            float v = L[7], vo;
            vo = __shfl_up_sync(FULL, v, 1);  if (lane >= 1)  v = fmaf(q,   vo, v);
            vo = __shfl_up_sync(FULL, v, 2);  if (lane >= 2)  v = fmaf(q2,  vo, v);
            vo = __shfl_up_sync(FULL, v, 4);  if (lane >= 4)  v = fmaf(q4,  vo, v);
            vo = __shfl_up_sync(FULL, v, 8);  if (lane >= 8)  v = fmaf(q8,  vo, v);
            vo = __shfl_up_sync(FULL, v, 16); if (lane >= 16) v = fmaf(q16, vo, v);
            float vprev = __shfl_up_sync(FULL, v, 1);
            if (lane == 0) vprev = 0.f;
            float C = fmaf(blE, warpCarry, vprev);

            float F[8];
            {
                float coef = BETA;
                #pragma unroll
                for (int j = 0; j < 8; j++) { F[j] = fmaf(coef, C, L[j]); coef *= BETA; }
            }
            float v31 = __shfl_sync(FULL, v, 31);
            warpCarry = fmaf(B256, warpCarry, v31);

            if (tt < hi) {
                *(float4*)(srow + tb - 7) = make_float4(0.5f*F[7], 0.5f*F[6], 0.5f*F[5], 0.5f*F[4]);
                *(float4*)(srow + tb - 3) = make_float4(0.5f*F[3], 0.5f*F[2], 0.5f*F[1], 0.5f*F[0]);
            }
        }
    }
}

// ---------------------------------------------------------------------------
// G: split-bf16 tensor-core GEMM with bias folded into K-channel 32 and
// accumulators stored DIRECTLY to global (no shared epilogue round-trip).
// D = Sh*Wh + Sh*Wl + Sl*Wh over padded K=48; Sh[.,32]=1 carries the bias.
// Block: 256 thr (8 warps), tile 128 t x 512 e (e in 4 chunks of 128).
// ---------------------------------------------------------------------------
__global__ void __launch_bounds__(256) gemm_kernel(float* __restrict__ out)
{
    __shared__ __nv_bfloat16 Sh[128][KP];   // [t][k], ld 48
    __shared__ __nv_bfloat16 Sl[128][32];   // lo residual only needs k<32
    __shared__ __nv_bfloat16 Wh[128][KP];   // [e_local][k]
    __shared__ __nv_bfloat16 Wl[128][KP];

    int tid  = threadIdx.x;
    int warp = tid >> 5;
    int b = blockIdx.y;
    int tBase = blockIdx.x * 128;

    // Load s tile: 128t x 32c; coalesced in t.
    #pragma unroll
    for (int k = 0; k < 16; k++) {
        int idx = tid + k * 256;
        int t = idx & 127;
        int c = idx >> 7;
        size_t off = ((size_t)(b * Cc + c)) * Tt + tBase + t;
        float s = g_sA[off] + g_sB[off];
        __nv_bfloat16 h = __float2bfloat16(s);
        Sh[t][c] = h;
        Sl[t][c] = __float2bfloat16(s - __bfloat162float(h));
    }
    // Pad columns 32..47 of Sh: bias channel (=1) then zeros.
    #pragma unroll
    for (int k = 0; k < 8; k++) {
        int idx = tid + k * 256;          // 0..2047 = 128t x 16c
        int t = idx & 127;
        int c = 32 + (idx >> 7);
        Sh[t][c] = __float2bfloat16(c == 32 ? 1.f : 0.f);
    }
    __syncthreads();

    // Per-warp A fragments (reused across all e)
    wmma::fragment<wmma::matrix_a, 16, 16, 16, __nv_bfloat16, wmma::row_major> ah0, ah1, ah2, al0, al1;
    wmma::load_matrix_sync(ah0, &Sh[warp * 16][0],  KP);
    wmma::load_matrix_sync(ah1, &Sh[warp * 16][16], KP);
    wmma::load_matrix_sync(ah2, &Sh[warp * 16][32], KP);
    wmma::load_matrix_sync(al0, &Sl[warp * 16][0],  32);
    wmma::load_matrix_sync(al1, &Sl[warp * 16][16], 32);

    for (int ch = 0; ch < 4; ch++) {
        int eBase = ch * 128;
        __syncthreads();   // previous chunk readers done with Wh/Wl
        // Copy W chunk: 128 rows x 48 bf16 = 3072 ints each, contiguous.
        {
            const int* srcH = (const int*)(g_whi + (size_t)eBase * KP);
            const int* srcL = (const int*)(g_wlo + (size_t)eBase * KP);
            int* dstH = (int*)&Wh[0][0];
            int* dstL = (int*)&Wl[0][0];
            #pragma unroll
            for (int k = 0; k < 12; k++) {
                dstH[tid + k * 256] = srcH[tid + k * 256];
                dstL[tid + k * 256] = srcL[tid + k * 256];
            }
        }
        __syncthreads();

        #pragma unroll
        for (int et = 0; et < 8; et++) {
            wmma::fragment<wmma::matrix_b, 16, 16, 16, __nv_bfloat16, wmma::col_major> bh0, bh1, bh2, bl0, bl1, bl2;
            wmma::load_matrix_sync(bh0, &Wh[et * 16][0],  KP);
            wmma::load_matrix_sync(bh1, &Wh[et * 16][16], KP);
            wmma::load_matrix_sync(bh2, &Wh[et * 16][32], KP);
            wmma::load_matrix_sync(bl0, &Wl[et * 16][0],  KP);
            wmma::load_matrix_sync(bl1, &Wl[et * 16][16], KP);
            wmma::load_matrix_sync(bl2, &Wl[et * 16][32], KP);

            wmma::fragment<wmma::accumulator, 16, 16, 16, float> acc;
            wmma::fill_fragment(acc, 0.f);
            wmma::mma_sync(acc, ah0, bh0, acc);
            wmma::mma_sync(acc, ah1, bh1, acc);
            wmma::mma_sync(acc, ah2, bh2, acc);   // + bias(hi)
            wmma::mma_sync(acc, ah0, bl0, acc);
            wmma::mma_sync(acc, ah1, bl1, acc);
            wmma::mma_sync(acc, ah2, bl2, acc);   // + bias(lo)
            wmma::mma_sync(acc, al0, bh0, acc);
            wmma::mma_sync(acc, al1, bh1, acc);

            // Direct store: rows are 16 contiguous floats (2 full sectors).
            float* dst = out + ((size_t)(b * Tt + tBase + warp * 16)) * Dd
                             + eBase + et * 16;
            wmma::store_matrix_sync(dst, acc, Dd, wmma::mem_row_major);
        }
    }
}

// ---------------------------------------------------------------------------
extern "C" void kernel_launch(void* const* d_in, const int* in_sizes, int n_in,
                              void* d_out, int out_size)
{
    const float* x     = (const float*)d_in[0];   // [B, C, T]
    const float* W_ve  = (const float*)d_in[1];   // [D, C]
    const float* b_ve  = (const float*)d_in[2];   // [D]
    const float* W_lin = (const float*)d_in[3];   // [D, D]
    const float* b_lin = (const float*)d_in[4];   // [D]
    float* out = (float*)d_out;                   // [B, T, D]

    // S: 16384 segment-warps (rows x 8 segs x 2 dirs), 8 warps/block
    scan_kernel<<<(Bb * Cc * NSEG * 2) / 8, 256>>>(x);

    // P: compose linears, bf16 split, padded + bias channel
    prep_kernel<<<Dd, 256>>>(W_ve, b_ve, W_lin, b_lin);

    // G: tensor-core GEMM, bias fused, direct stores
    dim3 grid(Tt / 128, Bb);
    gemm_kernel<<<grid, 256>>>(out);
}

// round 7
// speedup vs baseline: 1.1462x; 1.1000x over previous
#include <cuda_runtime.h>
#include <cstdint>

#define Bb 32
#define Cc 32
#define Tt 2048
#define Dd 512
#define ALPHA 0.1f
#define BETA  0.9f

#define SEG   256
#define NSEG  (Tt / SEG)

// Scratch (no cudaMalloc allowed)
__device__ float g_sA[Bb*Cc*Tt];      // 0.5 * forward EWMA of diff   [b][c][t]
__device__ float g_sB[Bb*Cc*Tt];      // 0.5 * backward EWMA of diff  [b][c][t]
__device__ float g_wc[Cc*Dd];         // Wcomb c-major: g_wc[c*Dd + e]
__device__ float g_bcomb[Dd];         // W_lin @ b_ve + b_lin

#define FMA_F32X2(d, a, b, c) \
    asm("fma.rn.f32x2 %0, %1, %2, %3;" : "=l"(d) : "l"(a), "l"(b), "l"(c))

static __device__ __forceinline__ float2 unpack_f32x2(unsigned long long v) {
    float2 r;
    asm("mov.b64 {%0, %1}, %2;" : "=f"(r.x), "=f"(r.y) : "l"(v));
    return r;
}

// ---------------------------------------------------------------------------
// P: compose linears. One block per output row e; Wcomb stored c-major.
// ---------------------------------------------------------------------------
__global__ void __launch_bounds__(256) prep_kernel(
    const float* __restrict__ W_ve, const float* __restrict__ b_ve,
    const float* __restrict__ W_lin, const float* __restrict__ b_lin)
{
    __shared__ float wl[Dd];
    int e = blockIdx.x;
    int tid = threadIdx.x;
    wl[tid]       = W_lin[(size_t)e * Dd + tid];
    wl[tid + 256] = W_lin[(size_t)e * Dd + tid + 256];
    __syncthreads();

    int wj   = tid >> 5;
    int lane = tid & 31;
    const unsigned FULL = 0xffffffffu;

    for (int c = wj; c <= Cc; c += 8) {
        float acc = 0.f;
        if (c < Cc) {
            #pragma unroll
            for (int i = 0; i < 16; i++) {
                int d = lane + 32 * i;
                acc = fmaf(wl[d], W_ve[d * Cc + c], acc);
            }
        } else {
            #pragma unroll
            for (int i = 0; i < 16; i++) {
                int d = lane + 32 * i;
                acc = fmaf(wl[d], b_ve[d], acc);
            }
        }
        acc += __shfl_down_sync(FULL, acc, 16);
        acc += __shfl_down_sync(FULL, acc, 8);
        acc += __shfl_down_sync(FULL, acc, 4);
        acc += __shfl_down_sync(FULL, acc, 2);
        acc += __shfl_down_sync(FULL, acc, 1);
        if (lane == 0) {
            if (c < Cc) g_wc[c * Dd + e] = acc;
            else        g_bcomb[e] = acc + b_lin[e];
        }
    }
}

// ---------------------------------------------------------------------------
// S: bidirectional EWMA of first-difference (unchanged).
// ---------------------------------------------------------------------------
__global__ void __launch_bounds__(256) scan_kernel(const float* __restrict__ x)
{
    const unsigned FULL = 0xffffffffu;
    int g    = blockIdx.x * 8 + (threadIdx.x >> 5);
    int lane = threadIdx.x & 31;
    int bc   = g >> 4;
    int rem  = g & 15;
    int seg  = rem >> 1;
    int dir  = rem & 1;

    const float* row = x + (size_t)bc * Tt;
    int lo = seg * SEG;
    int hi = lo + SEG;

    const float q   = 0.43046721f;              // 0.9^8
    const float q2  = q * q;
    const float q4  = q2 * q2;
    const float q8  = q4 * q4;
    const float q16 = q8 * q8;
    float blE;
    {
        float p = 1.f, base = q;
        int n = lane;
        while (n) { if (n & 1) p *= base; base *= base; n >>= 1; }
        blE = p;
    }
    const float B256 = 1.9e-12f;

    if (dir == 0) {
        float* srow = g_sA + (size_t)bc * Tt;
        int t0 = (seg == 0) ? lo : (lo - SEG);
        float warpCarry = 0.f;
        for (; t0 < hi; t0 += SEG) {
            int tb = t0 + lane * 8;
            float4 a  = *(const float4*)(row + tb);
            float4 bq = *(const float4*)(row + tb + 4);
            float e[8] = {a.x, a.y, a.z, a.w, bq.x, bq.y, bq.z, bq.w};
            float prev = __shfl_up_sync(FULL, bq.w, 1);
            if (lane == 0) prev = (tb > 0) ? row[tb - 1] : 0.f;

            float L[8];
            L[0] = (tb == 0) ? 0.f : ALPHA * (e[0] - prev);
            #pragma unroll
            for (int j = 1; j < 8; j++)
                L[j] = fmaf(BETA, L[j - 1], ALPHA * (e[j] - e[j - 1]));

            float v = L[7], vo;
            vo = __shfl_up_sync(FULL, v, 1);  if (lane >= 1)  v = fmaf(q,   vo, v);
            vo = __shfl_up_sync(FULL, v, 2);  if (lane >= 2)  v = fmaf(q2,  vo, v);
            vo = __shfl_up_sync(FULL, v, 4);  if (lane >= 4)  v = fmaf(q4,  vo, v);
            vo = __shfl_up_sync(FULL, v, 8);  if (lane >= 8)  v = fmaf(q8,  vo, v);
            vo = __shfl_up_sync(FULL, v, 16); if (lane >= 16) v = fmaf(q16, vo, v);
            float vprev = __shfl_up_sync(FULL, v, 1);
            if (lane == 0) vprev = 0.f;
            float C = fmaf(blE, warpCarry, vprev);

            float F[8];
            float coef = BETA;
            #pragma unroll
            for (int j = 0; j < 8; j++) { F[j] = fmaf(coef, C, L[j]); coef *= BETA; }
            float v31 = __shfl_sync(FULL, v, 31);
            warpCarry = fmaf(B256, warpCarry, v31);

            if (t0 >= lo) {
                *(float4*)(srow + tb)     = make_float4(0.5f*F[0], 0.5f*F[1], 0.5f*F[2], 0.5f*F[3]);
                *(float4*)(srow + tb + 4) = make_float4(0.5f*F[4], 0.5f*F[5], 0.5f*F[6], 0.5f*F[7]);
            }
        }
    } else {
        float* srow = g_sB + (size_t)bc * Tt;
        bool last = (hi == Tt);
        int tt = last ? (Tt - 1) : (hi + SEG - 1);
        float warpCarry = last ? (row[Tt - 1] - row[Tt - 2]) : 0.f;
        for (; tt >= lo; tt -= SEG) {
            int tb = tt - lane * 8;
            float4 a  = *(const float4*)(row + tb - 7);
            float4 bq = *(const float4*)(row + tb - 3);
            float e[8] = {bq.w, bq.z, bq.y, bq.x, a.w, a.z, a.y, a.x};
            float prev = __shfl_down_sync(FULL, bq.w, 1);
            if (lane == 31) prev = (tb - 8 >= 0) ? row[tb - 8] : 0.f;

            float L[8];
            L[0] = ALPHA * (e[0] - e[1]);
            #pragma unroll
            for (int j = 1; j < 7; j++)
                L[j] = fmaf(BETA, L[j - 1], ALPHA * (e[j] - e[j + 1]));
            {
                float d7 = (tb - 7 == 0) ? 0.f : (e[7] - prev);
                L[7] = fmaf(BETA, L[6], ALPHA * d7);
            }

            float v = L[7], vo;
            vo = __shfl_up_sync(FULL, v, 1);  if (lane >= 1)  v = fmaf(q,   vo, v);
            vo = __shfl_up_sync(FULL, v, 2);  if (lane >= 2)  v = fmaf(q2,  vo, v);
            vo = __shfl_up_sync(FULL, v, 4);  if (lane >= 4)  v = fmaf(q4,  vo, v);
            vo = __shfl_up_sync(FULL, v, 8);  if (lane >= 8)  v = fmaf(q8,  vo, v);
            vo = __shfl_up_sync(FULL, v, 16); if (lane >= 16) v = fmaf(q16, vo, v);
            float vprev = __shfl_up_sync(FULL, v, 1);
            if (lane == 0) vprev = 0.f;
            float C = fmaf(blE, warpCarry, vprev);

            float F[8];
            float coef = BETA;
            #pragma unroll
            for (int j = 0; j < 8; j++) { F[j] = fmaf(coef, C, L[j]); coef *= BETA; }
            float v31 = __shfl_sync(FULL, v, 31);
            warpCarry = fmaf(B256, warpCarry, v31);

            if (tt < hi) {
                *(float4*)(srow + tb - 7) = make_float4(0.5f*F[7], 0.5f*F[6], 0.5f*F[5], 0.5f*F[4]);
                *(float4*)(srow + tb - 3) = make_float4(0.5f*F[3], 0.5f*F[2], 0.5f*F[1], 0.5f*F[0]);
            }
        }
    }
}

// ---------------------------------------------------------------------------
// G: register-blocked FFMA2 GEMM.
// Block tile 128t x 128e, 256 threads (tx 0..15 -> e, ty 0..15 -> t).
// Thread tile: 8 t x 8 e. e's = eBase + 2*tx + 32*p + q (p=0..3, q=0..1).
// Accumulators are f32x2 pairs over q; per c: s duplicated-pair loads
// (broadcast, 2 distinct addrs/warp) x4 LDS.128, w natural pairs x4 LDS.64
// (conflict-free), 32 FFMA2.
// ---------------------------------------------------------------------------
__global__ void __launch_bounds__(256) gemm_kernel(float* __restrict__ out)
{
    __shared__ float2 dssm[Cc][128];   // [c][t_local] duplicated (v,v), 32 KB
    __shared__ float  wsm[Cc][128];    // [c][e_local] natural, 16 KB

    int tid = threadIdx.x;
    int tx = tid & 15;
    int ty = tid >> 4;
    int b = blockIdx.z;
    int eBase = blockIdx.y * 128;
    int tBase = blockIdx.x * 128;

    // Stage s: 32c x 128t; coalesced float4 over t; store duplicated pairs.
    #pragma unroll
    for (int k = 0; k < 4; k++) {
        int idx = tid + k * 256;          // 0..1023
        int c   = idx >> 5;               // 0..31
        int tl  = (idx & 31) * 4;         // 0..124
        size_t off = ((size_t)(b * Cc + c)) * Tt + tBase + tl;
        float4 a  = *(const float4*)(g_sA + off);
        float4 bq = *(const float4*)(g_sB + off);
        float v0 = a.x + bq.x, v1 = a.y + bq.y, v2 = a.z + bq.z, v3 = a.w + bq.w;
        float4* d = (float4*)&dssm[c][tl];
        d[0] = make_float4(v0, v0, v1, v1);
        d[1] = make_float4(v2, v2, v3, v3);
    }
    // Stage w: 32c x 128e, natural layout.
    #pragma unroll
    for (int k = 0; k < 4; k++) {
        int idx = tid + k * 256;
        int c   = idx >> 5;
        int e4  = (idx & 31) * 4;
        *(float4*)&wsm[c][e4] = *(const float4*)(g_wc + (size_t)c * Dd + eBase + e4);
    }
    __syncthreads();

    unsigned long long acc[8][4];
    #pragma unroll
    for (int i = 0; i < 8; i++)
        #pragma unroll
        for (int p = 0; p < 4; p++) acc[i][p] = 0ull;

    #pragma unroll
    for (int c = 0; c < Cc; c++) {
        const ulonglong2* sp = (const ulonglong2*)&dssm[c][ty * 8];
        ulonglong2 s01 = sp[0];
        ulonglong2 s23 = sp[1];
        ulonglong2 s45 = sp[2];
        ulonglong2 s67 = sp[3];
        unsigned long long sv[8] = {s01.x, s01.y, s23.x, s23.y,
                                    s45.x, s45.y, s67.x, s67.y};
        unsigned long long w0 = *(const unsigned long long*)&wsm[c][2 * tx];
        unsigned long long w1 = *(const unsigned long long*)&wsm[c][2 * tx + 32];
        unsigned long long w2 = *(const unsigned long long*)&wsm[c][2 * tx + 64];
        unsigned long long w3 = *(const unsigned long long*)&wsm[c][2 * tx + 96];
        #pragma unroll
        for (int i = 0; i < 8; i++) {
            FMA_F32X2(acc[i][0], sv[i], w0, acc[i][0]);
            FMA_F32X2(acc[i][1], sv[i], w1, acc[i][1]);
            FMA_F32X2(acc[i][2], sv[i], w2, acc[i][2]);
            FMA_F32X2(acc[i][3], sv[i], w3, acc[i][3]);
        }
    }

    // Epilogue: bias + float2 stores (contiguous 128B runs per (t,p)).
    float2 bias[4];
    #pragma unroll
    for (int p = 0; p < 4; p++)
        bias[p] = *(const float2*)(g_bcomb + eBase + 2 * tx + 32 * p);

    #pragma unroll
    for (int i = 0; i < 8; i++) {
        int t = tBase + ty * 8 + i;
        float* base = out + ((size_t)(b * Tt + t)) * Dd + eBase;
        #pragma unroll
        for (int p = 0; p < 4; p++) {
            float2 r = unpack_f32x2(acc[i][p]);
            r.x += bias[p].x;
            r.y += bias[p].y;
            *(float2*)(base + 2 * tx + 32 * p) = r;
        }
    }
}

// ---------------------------------------------------------------------------
extern "C" void kernel_launch(void* const* d_in, const int* in_sizes, int n_in,
                              void* d_out, int out_size)
{
    const float* x     = (const float*)d_in[0];   // [B, C, T]
    const float* W_ve  = (const float*)d_in[1];   // [D, C]
    const float* b_ve  = (const float*)d_in[2];   // [D]
    const float* W_lin = (const float*)d_in[3];   // [D, D]
    const float* b_lin = (const float*)d_in[4];   // [D]
    float* out = (float*)d_out;                   // [B, T, D]

    scan_kernel<<<(Bb * Cc * NSEG * 2) / 8, 256>>>(x);
    prep_kernel<<<Dd, 256>>>(W_ve, b_ve, W_lin, b_lin);

    dim3 grid(Tt / 128, Dd / 128, Bb);
    gemm_kernel<<<grid, 256>>>(out);
}